// round 14
// baseline (speedup 1.0000x reference)
#include <cuda_runtime.h>
#include <math.h>

#define N_NODES 50000
#define N_EDGES 1600000
#define IN_DIM  128
#define HID     64
#define EPS     1e-6f

typedef unsigned long long u64;

// ---------------- device scratch (static; 16B-aligned) ----------------
__device__ __align__(16) int   g_csrc[N_EDGES];     // CSR: src grouped by dst
__device__ __align__(16) int   g_row [N_NODES + 1]; // CSR row offsets
__device__ __align__(16) int   g_cur [N_NODES];     // scatter cursors
__device__ __align__(16) int   g_degi[N_NODES];
__device__ __align__(16) float g_invdeg[N_NODES];
__device__ __align__(16) float g_H [N_NODES * HID]; // layer output h
__device__ __align__(16) float g_Hs[N_NODES * HID]; // h @ ws
__device__ __align__(16) float g_Hn[N_NODES * HID]; // h @ wn

// ---------------- packed f32x2 helpers (sm_103a FFMA2) ----------------
__device__ __forceinline__ u64 pack2(float v) {
    u64 r; asm("mov.b64 %0, {%1, %1};" : "=l"(r) : "f"(v)); return r;
}
__device__ __forceinline__ void fma2(u64& d, u64 a, u64 b) {
    asm("fma.rn.f32x2 %0, %1, %2, %3;" : "=l"(d) : "l"(a), "l"(b), "l"(d));
}

// ---------------- prep ----------------
__global__ void k_zero_deg() {
    int i = blockIdx.x * blockDim.x + threadIdx.x;
    if (i < N_NODES) g_degi[i] = 0;
}

// degree count only: read dst row of edge_index (int4-vectorized)
__global__ void k_deg(const int* __restrict__ ei) {
    int q = blockIdx.x * blockDim.x + threadIdx.x;
    if (q >= N_EDGES / 4) return;
    int4 d4 = ((const int4*)(ei + N_EDGES))[q];
    atomicAdd(&g_degi[min(max(d4.x, 0), N_NODES - 1)], 1);
    atomicAdd(&g_degi[min(max(d4.y, 0), N_NODES - 1)], 1);
    atomicAdd(&g_degi[min(max(d4.z, 0), N_NODES - 1)], 1);
    atomicAdd(&g_degi[min(max(d4.w, 0), N_NODES - 1)], 1);
}

// single-block exclusive scan of g_degi -> g_row, g_cur; also invdeg
__global__ void k_scan() {
    __shared__ int warpsums[32];
    const int CH = (N_NODES + 1023) / 1024;  // 49
    int t    = threadIdx.x;
    int lane = t & 31;
    int wid  = t >> 5;
    int base = t * CH;

    int local = 0;
    for (int i = 0; i < CH; i++) {
        int idx = base + i;
        if (idx < N_NODES) local += g_degi[idx];
    }
    int v = local;
#pragma unroll
    for (int o = 1; o < 32; o <<= 1) {
        int n = __shfl_up_sync(0xffffffffu, v, o);
        if (lane >= o) v += n;
    }
    if (lane == 31) warpsums[wid] = v;
    __syncthreads();
    if (wid == 0) {
        int w = warpsums[lane];
#pragma unroll
        for (int o = 1; o < 32; o <<= 1) {
            int n = __shfl_up_sync(0xffffffffu, w, o);
            if (lane >= o) w += n;
        }
        warpsums[lane] = w;
    }
    __syncthreads();
    int run = v - local + (wid > 0 ? warpsums[wid - 1] : 0);  // exclusive prefix
    for (int i = 0; i < CH; i++) {
        int idx = base + i;
        if (idx < N_NODES) {
            g_row[idx] = run;
            g_cur[idx] = run;
            int dg = g_degi[idx];
            g_invdeg[idx] = 1.0f / fmaxf((float)dg, 1.0f);
            run += dg;
        }
    }
    if (t == 1023) g_row[N_NODES] = N_EDGES;
}

// scatter src into dst-grouped order, reading edge_index directly
__global__ void k_scatter(const int* __restrict__ ei) {
    int e = blockIdx.x * blockDim.x + threadIdx.x;
    if (e >= N_EDGES) return;
    int s = min(max(ei[e], 0), N_NODES - 1);
    int d = min(max(ei[N_EDGES + e], 0), N_NODES - 1);
    int p = atomicAdd(&g_cur[d], 1);
    g_csrc[p] = s;
}

// ---------------- fused dual GEMM: Hs = Hin@Ws, Hn = Hin@Wn ----------------
// 64x64 tile, 256 threads as 16x16; 4-row x 4-col register tile per thread for
// both outputs, accumulated as packed f32x2 (FFMA2 -> half the fma-pipe cycles).
template <int K>
__global__ void k_gemm2(const float* __restrict__ xin,
                        const float* __restrict__ Ws,
                        const float* __restrict__ Wn,
                        int srcSel) {
    __shared__ __align__(16) float sHt[64][33];   // [row][k] padded
    __shared__ __align__(16) float sWs[32][64];
    __shared__ __align__(16) float sWn[32][64];

    const float* Hin = srcSel ? (const float*)g_H : xin;
    int t  = threadIdx.x;
    int tx = t & 15;         // col group (4 cols = 2 packed pairs)
    int ty = t >> 4;         // row group (4 rows)
    int rowBase = blockIdx.x * 64;

    u64 acc_s2[4][2] = {{0ull, 0ull}, {0ull, 0ull}, {0ull, 0ull}, {0ull, 0ull}};
    u64 acc_n2[4][2] = {{0ull, 0ull}, {0ull, 0ull}, {0ull, 0ull}, {0ull, 0ull}};

    for (int k0 = 0; k0 < K; k0 += 32) {
        {
            int lane = t & 31, w = t >> 5;
            for (int r = w; r < 64; r += 8) {
                int gr = rowBase + r;
                sHt[r][lane] = (gr < N_NODES) ? Hin[(size_t)gr * K + k0 + lane] : 0.f;
            }
            for (int i = t; i < 32 * 64; i += 256) {
                ((float*)sWs)[i] = Ws[k0 * HID + i];
                ((float*)sWn)[i] = Wn[k0 * HID + i];
            }
        }
        __syncthreads();

#pragma unroll
        for (int kk = 0; kk < 32; kk++) {
            u64 a2[4];
#pragma unroll
            for (int i = 0; i < 4; i++) a2[i] = pack2(sHt[ty * 4 + i][kk]);
            ulonglong2 bs2 = *(const ulonglong2*)&sWs[kk][tx * 4];
            ulonglong2 bn2 = *(const ulonglong2*)&sWn[kk][tx * 4];
#pragma unroll
            for (int i = 0; i < 4; i++) {
                fma2(acc_s2[i][0], a2[i], bs2.x);
                fma2(acc_s2[i][1], a2[i], bs2.y);
                fma2(acc_n2[i][0], a2[i], bn2.x);
                fma2(acc_n2[i][1], a2[i], bn2.y);
            }
        }
        __syncthreads();
    }

#pragma unroll
    for (int i = 0; i < 4; i++) {
        int gr = rowBase + ty * 4 + i;
        if (gr < N_NODES) {
            ulonglong2 vs; vs.x = acc_s2[i][0]; vs.y = acc_s2[i][1];
            ulonglong2 vn; vn.x = acc_n2[i][0]; vn.y = acc_n2[i][1];
            *(ulonglong2*)&g_Hs[(size_t)gr * HID + tx * 4] = vs;
            *(ulonglong2*)&g_Hn[(size_t)gr * HID + tx * 4] = vn;
        }
    }
}

// ---------------- fused pull-aggregate + finalize -> g_H ----------------
__global__ void k_aggfin() {
    unsigned gt   = blockIdx.x * blockDim.x + threadIdx.x;
    unsigned node = gt >> 5;
    unsigned lane = gt & 31;
    if (node >= N_NODES) return;

    const int* __restrict__ csrc = g_csrc;
    const float* __restrict__ Hn = g_Hn;
    int beg = g_row[node];
    int end = g_row[node + 1];
    float s0 = 0.f, s1 = 0.f;
    int i = beg;
    for (; i + 3 < end; i += 4) {
        int sA = csrc[i], sB = csrc[i + 1], sC = csrc[i + 2], sD = csrc[i + 3];
        const float* rA = Hn + (size_t)sA * HID;
        const float* rB = Hn + (size_t)sB * HID;
        const float* rC = Hn + (size_t)sC * HID;
        const float* rD = Hn + (size_t)sD * HID;
        float a0 = __ldg(rA + lane), a1 = __ldg(rA + lane + 32);
        float b0 = __ldg(rB + lane), b1 = __ldg(rB + lane + 32);
        float c0 = __ldg(rC + lane), c1 = __ldg(rC + lane + 32);
        float d0 = __ldg(rD + lane), d1 = __ldg(rD + lane + 32);
        s0 += (a0 + b0) + (c0 + d0);
        s1 += (a1 + b1) + (c1 + d1);
    }
    for (; i < end; i++) {
        int sA = csrc[i];
        const float* rA = Hn + (size_t)sA * HID;
        s0 += __ldg(rA + lane);
        s1 += __ldg(rA + lane + 32);
    }

    float inv = g_invdeg[node];
    size_t base = (size_t)node * HID;
    float a0 = fmaxf(g_Hs[base + lane]      + s0 * inv, 0.f);
    float a1 = fmaxf(g_Hs[base + lane + 32] + s1 * inv, 0.f);
    float ss = a0 * a0 + a1 * a1;
#pragma unroll
    for (int o = 16; o > 0; o >>= 1) ss += __shfl_xor_sync(0xffffffffu, ss, o);
    float r = 1.f / (sqrtf(ss) + EPS);
    g_H[base + lane]      = a0 * r;
    g_H[base + lane + 32] = a1 * r;
}

// ---------------- layer-2 aggregate + finalize + MLP head -> out ----------------
// same as k_aggfin but keeps h in smem and applies the MLP head directly.
__global__ void k_aggfin_mlp(const float* __restrict__ mw1, const float* __restrict__ mb1,
                             const float* __restrict__ mw2, const float* __restrict__ mb2,
                             float* __restrict__ out) {
    __shared__ float W1[HID * 32];
    __shared__ float W2[32];
    __shared__ float B1[32];
    __shared__ float hrow[8][HID];

    int t = threadIdx.x;
    for (int i = t; i < HID * 32; i += 256) W1[i] = mw1[i];
    if (t < 32) { W2[t] = mw2[t]; B1[t] = mb1[t]; }
    __syncthreads();

    unsigned gt   = blockIdx.x * blockDim.x + t;
    unsigned node = gt >> 5;
    unsigned wid  = (unsigned)(t >> 5);
    unsigned lane = gt & 31;
    if (node >= N_NODES) return;

    const int* __restrict__ csrc = g_csrc;
    const float* __restrict__ Hn = g_Hn;
    int beg = g_row[node];
    int end = g_row[node + 1];
    float s0 = 0.f, s1 = 0.f;
    int i = beg;
    for (; i + 3 < end; i += 4) {
        int sA = csrc[i], sB = csrc[i + 1], sC = csrc[i + 2], sD = csrc[i + 3];
        const float* rA = Hn + (size_t)sA * HID;
        const float* rB = Hn + (size_t)sB * HID;
        const float* rC = Hn + (size_t)sC * HID;
        const float* rD = Hn + (size_t)sD * HID;
        float a0 = __ldg(rA + lane), a1 = __ldg(rA + lane + 32);
        float b0 = __ldg(rB + lane), b1 = __ldg(rB + lane + 32);
        float c0 = __ldg(rC + lane), c1 = __ldg(rC + lane + 32);
        float d0 = __ldg(rD + lane), d1 = __ldg(rD + lane + 32);
        s0 += (a0 + b0) + (c0 + d0);
        s1 += (a1 + b1) + (c1 + d1);
    }
    for (; i < end; i++) {
        int sA = csrc[i];
        const float* rA = Hn + (size_t)sA * HID;
        s0 += __ldg(rA + lane);
        s1 += __ldg(rA + lane + 32);
    }

    float inv = g_invdeg[node];
    size_t base = (size_t)node * HID;
    float a0 = fmaxf(g_Hs[base + lane]      + s0 * inv, 0.f);
    float a1 = fmaxf(g_Hs[base + lane + 32] + s1 * inv, 0.f);
    float ss = a0 * a0 + a1 * a1;
#pragma unroll
    for (int o = 16; o > 0; o >>= 1) ss += __shfl_xor_sync(0xffffffffu, ss, o);
    float r = 1.f / (sqrtf(ss) + EPS);
    hrow[wid][lane]      = a0 * r;
    hrow[wid][lane + 32] = a1 * r;
    __syncwarp();

    float acc = B1[lane];
#pragma unroll 8
    for (int k = 0; k < HID; k++) acc += hrow[wid][k] * W1[k * 32 + lane];
    acc = fmaxf(acc, 0.f) * W2[lane];
#pragma unroll
    for (int o = 16; o > 0; o >>= 1) acc += __shfl_xor_sync(0xffffffffu, acc, o);
    if (lane == 0) out[node] = 1.f / (1.f + expf(-(acc + mb2[0])));
}

// ---------------- launch (pure kernel launches; nothing else) ----------------
extern "C" void kernel_launch(void* const* d_in, const int* in_sizes, int n_in,
                              void* d_out, int out_size) {
    const float* x   = (const float*)d_in[0];
    const int*   ei  = (const int*)d_in[1];     // int32 (harness dtype set)
    const float* w0s = (const float*)d_in[2];
    const float* w0n = (const float*)d_in[3];
    const float* w1s = (const float*)d_in[4];
    const float* w1n = (const float*)d_in[5];
    const float* w2s = (const float*)d_in[6];
    const float* w2n = (const float*)d_in[7];
    const float* mw1 = (const float*)d_in[8];
    const float* mb1 = (const float*)d_in[9];
    const float* mw2 = (const float*)d_in[10];
    const float* mb2 = (const float*)d_in[11];
    float*       out = (float*)d_out;

    const int TB = 256;
    // CSR build
    k_zero_deg<<<(N_NODES + TB - 1) / TB, TB>>>();
    k_deg<<<(N_EDGES / 4 + TB - 1) / TB, TB>>>(ei);
    k_scan<<<1, 1024>>>();
    k_scatter<<<(N_EDGES + TB - 1) / TB, TB>>>(ei);

    const int gemmBlocks = (N_NODES + 63) / 64;       // 782
    const int aggBlocks  = (N_NODES * 32 + TB - 1) / TB;

    // layer 0 (K = 128, input = x)
    k_gemm2<IN_DIM><<<gemmBlocks, TB>>>(x, w0s, w0n, 0);
    k_aggfin<<<aggBlocks, TB>>>();

    // layer 1
    k_gemm2<HID><<<gemmBlocks, TB>>>(nullptr, w1s, w1n, 1);
    k_aggfin<<<aggBlocks, TB>>>();

    // layer 2 (+ fused MLP head)
    k_gemm2<HID><<<gemmBlocks, TB>>>(nullptr, w2s, w2n, 1);
    k_aggfin_mlp<<<aggBlocks, TB>>>(mw1, mb1, mw2, mb2, out);
}